// round 1
// baseline (speedup 1.0000x reference)
#include <cuda_runtime.h>
#include <math.h>

#define EPS 1e-7f

// B=32, S=2048, D=1024
#define B_ 32
#define S_ 2048
#define D_ 1024

__device__ float g_proj[B_ * D_];   // [B, D] = y @ M^T
__device__ float g_sums[B_];        // per-batch sum of a

// ---------------------------------------------------------------------------
// Kernel 1: proj[b,e] = sum_d M[e,d] * y[b,d]
// Warp per e. M row held in registers (interleaved: lane l owns d = j*32 + l),
// loop over all 32 b reusing the M row. Also zeroes g_sums.
// grid: D_/8 blocks of 256 threads (8 warps -> 8 e per block)
// ---------------------------------------------------------------------------
__global__ void proj_kernel(const float* __restrict__ y,
                            const float* __restrict__ M) {
    if (blockIdx.x == 0 && threadIdx.x < B_) g_sums[threadIdx.x] = 0.0f;

    const int warp = threadIdx.x >> 5;
    const int lane = threadIdx.x & 31;
    const int e = blockIdx.x * 8 + warp;
    if (e >= D_) return;

    // load M[e, :] interleaved: m[j] = M[e, j*32 + lane]  (coalesced)
    float m[D_ / 32];
    const float* Mrow = M + (size_t)e * D_;
#pragma unroll
    for (int j = 0; j < D_ / 32; ++j) m[j] = Mrow[j * 32 + lane];

    for (int b = 0; b < B_; ++b) {
        const float* yrow = y + (size_t)b * D_;
        float acc = 0.0f;
#pragma unroll
        for (int j = 0; j < D_ / 32; ++j) acc = fmaf(m[j], yrow[j * 32 + lane], acc);
        // warp reduce
#pragma unroll
        for (int off = 16; off > 0; off >>= 1)
            acc += __shfl_xor_sync(0xFFFFFFFFu, acc, off);
        if (lane == 0) g_proj[b * D_ + e] = acc;
    }
}

// ---------------------------------------------------------------------------
// Kernel 2: a[b,s] = exp(tanh(dot(x[b,s,:], proj[b,:]))) * mask[b,s]
// Writes unnormalized a to out; block partial-sums atomicAdd into g_sums[b].
// grid: (S_/8, B_), block 256 threads (8 warps, warp per s-row).
// x streamed via float4 (8 independent loads/lane -> good MLP).
// ---------------------------------------------------------------------------
__global__ void eij_kernel(const float* __restrict__ x,
                           const int* __restrict__ mask,
                           float* __restrict__ out) {
    const int b = blockIdx.y;
    const int warp = threadIdx.x >> 5;
    const int lane = threadIdx.x & 31;
    const int s = blockIdx.x * 8 + warp;

    __shared__ float4 sp[D_ / 4];          // proj[b] as float4
    __shared__ float warp_partial[8];

    // stage proj[b] into shared (256 threads x 1 float4 each)
    const float4* pv = reinterpret_cast<const float4*>(g_proj + (size_t)b * D_);
    sp[threadIdx.x] = pv[threadIdx.x];
    __syncthreads();

    const float4* xv = reinterpret_cast<const float4*>(
        x + ((size_t)b * S_ + s) * D_);

    float acc = 0.0f;
#pragma unroll
    for (int j = 0; j < D_ / 128; ++j) {    // 8 iterations
        const int idx = j * 32 + lane;
        float4 xa = xv[idx];
        float4 pa = sp[idx];
        acc = fmaf(xa.x, pa.x, acc);
        acc = fmaf(xa.y, pa.y, acc);
        acc = fmaf(xa.z, pa.z, acc);
        acc = fmaf(xa.w, pa.w, acc);
    }
#pragma unroll
    for (int off = 16; off > 0; off >>= 1)
        acc += __shfl_xor_sync(0xFFFFFFFFu, acc, off);

    float a = 0.0f;
    if (lane == 0) {
        float e = tanhf(acc);
        a = __expf(e) * (float)mask[b * S_ + s];
        out[b * S_ + s] = a;
        warp_partial[warp] = a;
    }
    __syncthreads();

    // one warp reduces the 8 partials and does a single atomic per block
    if (threadIdx.x < 8) {
        float v = warp_partial[threadIdx.x];
#pragma unroll
        for (int off = 4; off > 0; off >>= 1)
            v += __shfl_xor_sync(0x000000FFu, v, off);
        if (threadIdx.x == 0) atomicAdd(&g_sums[b], v);
    }
}

// ---------------------------------------------------------------------------
// Kernel 3: out[b,s] /= (g_sums[b] + EPS)
// ---------------------------------------------------------------------------
__global__ void norm_kernel(float* __restrict__ out) {
    const int i = blockIdx.x * blockDim.x + threadIdx.x;
    if (i < B_ * S_) {
        const int b = i / S_;
        out[i] = out[i] / (g_sums[b] + EPS);
    }
}

extern "C" void kernel_launch(void* const* d_in, const int* in_sizes, int n_in,
                              void* d_out, int out_size) {
    const float* x    = (const float*)d_in[0];   // [32, 2048, 1024]
    const float* y    = (const float*)d_in[1];   // [32, 1024]
    const int*   mask = (const int*)d_in[2];     // [32, 2048]
    const float* M    = (const float*)d_in[3];   // [1024, 1024]
    float* out = (float*)d_out;                  // [32, 2048]

    proj_kernel<<<D_ / 8, 256>>>(y, M);
    dim3 g2(S_ / 8, B_);
    eij_kernel<<<g2, 256>>>(x, mask, out);
    norm_kernel<<<(B_ * S_ + 255) / 256, 256>>>(out);
}

// round 2
// speedup vs baseline: 2.3624x; 2.3624x over previous
#include <cuda_runtime.h>
#include <math.h>

#define EPS 1e-7f

// B=32, S=2048, D=1024
#define B_ 32
#define S_ 2048
#define D_ 1024

#define BSPLIT 8              // grid.y for proj: batches per warp = B_/BSPLIT = 4
#define BPW (B_ / BSPLIT)     // 4

__device__ float g_proj[B_ * D_];   // [B, D] = y @ M^T
__device__ float g_sums[B_];        // per-batch sum of a

// ---------------------------------------------------------------------------
// Kernel 1: proj[b,e] = sum_d M[e,d] * y[b,d]
// grid (D_/8, BSPLIT), block 256 (8 warps). Warp -> one e, BPW batches.
// M row in registers (lane-interleaved, coalesced); y from L1/L2.
// All BPW accumulators reduced with interleaved butterflies (independent
// shuffle chains overlap instead of serializing).
// ---------------------------------------------------------------------------
__global__ void proj_kernel(const float* __restrict__ y,
                            const float* __restrict__ M) {
    if (blockIdx.x == 0 && blockIdx.y == 0 && threadIdx.x < B_)
        g_sums[threadIdx.x] = 0.0f;

    const int warp = threadIdx.x >> 5;
    const int lane = threadIdx.x & 31;
    const int e = blockIdx.x * 8 + warp;
    const int b0 = blockIdx.y * BPW;

    // load M[e, :] interleaved: m[j] = M[e, j*32 + lane]  (coalesced)
    float m[D_ / 32];
    const float* Mrow = M + (size_t)e * D_;
#pragma unroll
    for (int j = 0; j < D_ / 32; ++j) m[j] = Mrow[j * 32 + lane];

    float acc[BPW];
#pragma unroll
    for (int bb = 0; bb < BPW; ++bb) acc[bb] = 0.0f;

#pragma unroll
    for (int bb = 0; bb < BPW; ++bb) {
        const float* yrow = y + (size_t)(b0 + bb) * D_;
#pragma unroll
        for (int j = 0; j < D_ / 32; ++j)
            acc[bb] = fmaf(m[j], yrow[j * 32 + lane], acc[bb]);
    }

    // interleaved butterfly reductions (chains overlap)
#pragma unroll
    for (int off = 16; off > 0; off >>= 1) {
#pragma unroll
        for (int bb = 0; bb < BPW; ++bb)
            acc[bb] += __shfl_xor_sync(0xFFFFFFFFu, acc[bb], off);
    }

    if (lane < BPW) g_proj[(b0 + lane) * D_ + e] = acc[lane];
}

// ---------------------------------------------------------------------------
// Kernel 2: a[b,s] = exp(tanh(dot(x[b,s,:], proj[b,:]))) * mask[b,s]
// Writes unnormalized a to out; block partial-sums atomicAdd into g_sums[b].
// grid: (S_/8, B_), block 256 (warp per s-row). x via float4 (MLP=8/lane).
// ---------------------------------------------------------------------------
__global__ void eij_kernel(const float* __restrict__ x,
                           const int* __restrict__ mask,
                           float* __restrict__ out) {
    const int b = blockIdx.y;
    const int warp = threadIdx.x >> 5;
    const int lane = threadIdx.x & 31;
    const int s = blockIdx.x * 8 + warp;

    __shared__ float4 sp[D_ / 4];          // proj[b] as float4
    __shared__ float warp_partial[8];

    const float4* pv = reinterpret_cast<const float4*>(g_proj + (size_t)b * D_);
    sp[threadIdx.x] = pv[threadIdx.x];
    __syncthreads();

    const float4* xv = reinterpret_cast<const float4*>(
        x + ((size_t)b * S_ + s) * D_);

    float acc = 0.0f;
#pragma unroll
    for (int j = 0; j < D_ / 128; ++j) {    // 8 iterations
        const int idx = j * 32 + lane;
        float4 xa = xv[idx];
        float4 pa = sp[idx];
        acc = fmaf(xa.x, pa.x, acc);
        acc = fmaf(xa.y, pa.y, acc);
        acc = fmaf(xa.z, pa.z, acc);
        acc = fmaf(xa.w, pa.w, acc);
    }
#pragma unroll
    for (int off = 16; off > 0; off >>= 1)
        acc += __shfl_xor_sync(0xFFFFFFFFu, acc, off);

    float a = 0.0f;
    if (lane == 0) {
        float e = tanhf(acc);
        a = __expf(e) * (float)mask[b * S_ + s];
        out[b * S_ + s] = a;
        warp_partial[warp] = a;
    }
    __syncthreads();

    if (threadIdx.x < 8) {
        float v = warp_partial[threadIdx.x];
#pragma unroll
        for (int off = 4; off > 0; off >>= 1)
            v += __shfl_xor_sync(0x000000FFu, v, off);
        if (threadIdx.x == 0) atomicAdd(&g_sums[b], v);
    }
}

// ---------------------------------------------------------------------------
// Kernel 3: out[b,s] /= (g_sums[b] + EPS)
// ---------------------------------------------------------------------------
__global__ void norm_kernel(float* __restrict__ out) {
    const int i = blockIdx.x * blockDim.x + threadIdx.x;
    if (i < B_ * S_) {
        const int b = i / S_;
        out[i] = out[i] / (g_sums[b] + EPS);
    }
}

extern "C" void kernel_launch(void* const* d_in, const int* in_sizes, int n_in,
                              void* d_out, int out_size) {
    const float* x    = (const float*)d_in[0];   // [32, 2048, 1024]
    const float* y    = (const float*)d_in[1];   // [32, 1024]
    const int*   mask = (const int*)d_in[2];     // [32, 2048]
    const float* M    = (const float*)d_in[3];   // [1024, 1024]
    float* out = (float*)d_out;                  // [32, 2048]

    dim3 g1(D_ / 8, BSPLIT);
    proj_kernel<<<g1, 256>>>(y, M);
    dim3 g2(S_ / 8, B_);
    eij_kernel<<<g2, 256>>>(x, mask, out);
    norm_kernel<<<(B_ * S_ + 255) / 256, 256>>>(out);
}